// round 1
// baseline (speedup 1.0000x reference)
#include <cuda_runtime.h>
#include <math.h>

#define B_    32
#define C1    1024
#define N1    512
#define N2    256
#define HW    1024          // 32*32
#define NPIX  (B_*HW)       // 32768
#define IMG   512
#define RS    384
#define NREG  3

// ---------- scratch (static device globals; no runtime allocation) ----------
__device__ float g_h1[(size_t)NPIX * N1];   // 64 MB
__device__ float g_h2[(size_t)NPIX * N2];   // 32 MB
__device__ float g_att[NPIX];
__device__ int   g_xy[B_ * NREG * 2];       // (y1, x1) per region

// ---------------- fp32 tiled GEMM + bias + ReLU ----------------
// C[M=32768, N] = relu(A[M,K] * W[N,K]^T + bias)
// A_FEAT: A is features [B, C, 32, 32]  -> A[p,k] = A[b*C*HW + k*HW + hw], p=b*HW+hw
// else:   A row-major [M, K]
template <bool A_FEAT>
__global__ __launch_bounds__(256, 2)
void gemm_relu_kernel(const float* __restrict__ A, const float* __restrict__ W,
                      const float* __restrict__ bias, float* __restrict__ out,
                      int K, int N)
{
    __shared__ float As[16][128];
    __shared__ float Bs[16][128];

    const int tid = threadIdx.x;
    const int tx = tid & 15;          // 0..15 -> 8 cols each
    const int ty = tid >> 4;          // 0..15 -> 8 rows each
    const int rowBase = blockIdx.y * 128;
    const int colBase = blockIdx.x * 128;

    float acc[8][8];
#pragma unroll
    for (int i = 0; i < 8; i++)
#pragma unroll
        for (int j = 0; j < 8; j++) acc[i][j] = 0.f;

    for (int kt = 0; kt < K; kt += 16) {
        // ---- load A tile ----
        if (A_FEAT) {
            const int b0  = rowBase >> 10;
            const int hw0 = rowBase & 1023;
            const float* Ab = A + (size_t)b0 * ((size_t)C1 * HW) + hw0;
#pragma unroll
            for (int l = 0; l < 8; l++) {
                int idx = l * 256 + tid;
                int i  = idx & 127;
                int kk = idx >> 7;
                As[kk][i] = Ab[(size_t)(kt + kk) * HW + i];
            }
        } else {
            const int pp = tid >> 1;
            const int kh = (tid & 1) * 8;
            const float* ap = A + (size_t)(rowBase + pp) * K + kt + kh;
            float4 v0 = *(const float4*)ap;
            float4 v1 = *(const float4*)(ap + 4);
            As[kh + 0][pp] = v0.x; As[kh + 1][pp] = v0.y;
            As[kh + 2][pp] = v0.z; As[kh + 3][pp] = v0.w;
            As[kh + 4][pp] = v1.x; As[kh + 5][pp] = v1.y;
            As[kh + 6][pp] = v1.z; As[kh + 7][pp] = v1.w;
        }
        // ---- load W tile ----
        {
            const int oo = tid >> 1;
            const int kh = (tid & 1) * 8;
            const float* bp = W + (size_t)(colBase + oo) * K + kt + kh;
            float4 v0 = *(const float4*)bp;
            float4 v1 = *(const float4*)(bp + 4);
            Bs[kh + 0][oo] = v0.x; Bs[kh + 1][oo] = v0.y;
            Bs[kh + 2][oo] = v0.z; Bs[kh + 3][oo] = v0.w;
            Bs[kh + 4][oo] = v1.x; Bs[kh + 5][oo] = v1.y;
            Bs[kh + 6][oo] = v1.z; Bs[kh + 7][oo] = v1.w;
        }
        __syncthreads();

#pragma unroll
        for (int k = 0; k < 16; k++) {
            float4 a0 = *(const float4*)&As[k][ty * 8];
            float4 a1 = *(const float4*)&As[k][ty * 8 + 4];
            float4 b0 = *(const float4*)&Bs[k][tx * 8];
            float4 b1 = *(const float4*)&Bs[k][tx * 8 + 4];
            float ar[8] = {a0.x, a0.y, a0.z, a0.w, a1.x, a1.y, a1.z, a1.w};
            float br[8] = {b0.x, b0.y, b0.z, b0.w, b1.x, b1.y, b1.z, b1.w};
#pragma unroll
            for (int i = 0; i < 8; i++)
#pragma unroll
                for (int j = 0; j < 8; j++)
                    acc[i][j] = fmaf(ar[i], br[j], acc[i][j]);
        }
        __syncthreads();
    }

    // ---- epilogue: bias + relu ----
    const int col0 = colBase + tx * 8;
    float bb[8];
#pragma unroll
    for (int j = 0; j < 8; j++) bb[j] = bias[col0 + j];

    const int row0 = rowBase + ty * 8;
#pragma unroll
    for (int i = 0; i < 8; i++) {
        float4 o0, o1;
        o0.x = fmaxf(acc[i][0] + bb[0], 0.f);
        o0.y = fmaxf(acc[i][1] + bb[1], 0.f);
        o0.z = fmaxf(acc[i][2] + bb[2], 0.f);
        o0.w = fmaxf(acc[i][3] + bb[3], 0.f);
        o1.x = fmaxf(acc[i][4] + bb[4], 0.f);
        o1.y = fmaxf(acc[i][5] + bb[5], 0.f);
        o1.z = fmaxf(acc[i][6] + bb[6], 0.f);
        o1.w = fmaxf(acc[i][7] + bb[7], 0.f);
        float* op = out + (size_t)(row0 + i) * N + col0;
        *(float4*)op       = o0;
        *(float4*)(op + 4) = o1;
    }
}

// ---------------- layer 3 (matvec) + sigmoid + CAM average ----------------
__global__ void att_kernel(const float* __restrict__ h2, const float* __restrict__ w3,
                           const float* __restrict__ b3, const float* __restrict__ cam,
                           float* __restrict__ att_out)
{
    int warp = threadIdx.x >> 5;
    int lane = threadIdx.x & 31;
    int p = blockIdx.x * 8 + warp;
    const float* row = h2 + (size_t)p * N2;
    float s = 0.f;
#pragma unroll
    for (int j = 0; j < N2; j += 32) s = fmaf(row[j + lane], w3[j + lane], s);
#pragma unroll
    for (int off = 16; off; off >>= 1)
        s += __shfl_down_sync(0xffffffffu, s, off);
    if (lane == 0) {
        float v = 1.f / (1.f + expf(-(s + b3[0])));
        float a = (v + cam[p]) * 0.5f;
        g_att[p] = a;
        att_out[p] = a;
    }
}

// ---------------- peak picking: 1 block per batch ----------------
__global__ void peaks_kernel(float* __restrict__ coords_out)
{
    __shared__ float sm[1024];
    __shared__ float rv[8];
    __shared__ int   ri[8];
    __shared__ int   s_fy, s_fx;

    const int b = blockIdx.x;
    const int t = threadIdx.x;   // 256 threads

    for (int i = t; i < 1024; i += 256) sm[i] = g_att[b * 1024 + i];
    __syncthreads();

    for (int k = 0; k < NREG; k++) {
        float best = -1.f;
        int bi = 1 << 30;
        for (int i = t; i < 1024; i += 256) {
            float v = sm[i];
            if (v > best) { best = v; bi = i; }   // strided i increasing -> first max kept
        }
#pragma unroll
        for (int off = 16; off; off >>= 1) {
            float ov = __shfl_down_sync(0xffffffffu, best, off);
            int   oi = __shfl_down_sync(0xffffffffu, bi, off);
            if (ov > best || (ov == best && oi < bi)) { best = ov; bi = oi; }
        }
        if ((t & 31) == 0) { rv[t >> 5] = best; ri[t >> 5] = bi; }
        __syncthreads();
        if (t == 0) {
            for (int w = 1; w < 8; w++)
                if (rv[w] > best || (rv[w] == best && ri[w] < bi)) { best = rv[w]; bi = ri[w]; }
            int fy = bi >> 5, fx = bi & 31;
            if (!(best > 0.f)) { fy = 16; fx = 16; }
            int y1 = min(max(fy * 16 - (RS / 2), 0), IMG - RS);
            int x1 = min(max(fx * 16 - (RS / 2), 0), IMG - RS);
            int r = b * NREG + k;
            g_xy[r * 2 + 0] = y1;
            g_xy[r * 2 + 1] = x1;
            float* cp = coords_out + r * 4;
            cp[0] = (float)x1;
            cp[1] = (float)y1;
            cp[2] = (float)(x1 + RS);
            cp[3] = (float)(y1 + RS);
            s_fy = fy; s_fx = fx;
        }
        __syncthreads();
        int fy = s_fy, fx = s_fx;
        for (int i = t; i < 1024; i += 256) {
            int y = i >> 5, x = i & 31;
            if (abs(y - fy) <= 5 && abs(x - fx) <= 5) sm[i] = 0.f;
        }
        __syncthreads();
    }
}

// ---------------- region crops (memory-bound copy) ----------------
__global__ void crop_kernel(const float* __restrict__ orig, float* __restrict__ out)
{
    const int r = blockIdx.y;           // 0..95
    const int b = r / NREG;
    const int y1 = g_xy[r * 2 + 0];
    const int x1 = g_xy[r * 2 + 1];     // multiple of 16 -> float4 aligned

    int idx = blockIdx.x * blockDim.x + threadIdx.x;  // float4 index within region
    // region = 3 * 384 * 384 floats = 3*384*96 float4 = 110592
    int col4 = idx % 96;
    int tmp  = idx / 96;
    int row  = tmp % RS;
    int c    = tmp / RS;

    const float* src = orig + (((size_t)(b * 3 + c) * IMG) + (y1 + row)) * IMG + x1;
    float4 v = *((const float4*)src + col4);
    float4* dst = (float4*)(out + (size_t)r * (3 * RS * RS)) + idx;
    *dst = v;
}

// ---------------- launch ----------------
extern "C" void kernel_launch(void* const* d_in, const int* in_sizes, int n_in,
                              void* d_out, int out_size)
{
    const float* features = (const float*)d_in[0];
    const float* cam      = (const float*)d_in[1];
    const float* original = (const float*)d_in[2];
    const float* w1 = (const float*)d_in[3];
    const float* b1 = (const float*)d_in[4];
    const float* w2 = (const float*)d_in[5];
    const float* b2 = (const float*)d_in[6];
    const float* w3 = (const float*)d_in[7];
    const float* b3 = (const float*)d_in[8];

    float* out = (float*)d_out;
    const size_t regions_elems = (size_t)B_ * NREG * 3 * RS * RS;  // 42467328
    float* coords_out = out + regions_elems;                       // 384 floats
    float* att_out    = coords_out + (size_t)B_ * NREG * 4;        // 32768 floats

    float* h1;  cudaGetSymbolAddress((void**)&h1, g_h1);
    float* h2;  cudaGetSymbolAddress((void**)&h2, g_h2);

    // GEMM1: [32768,1024] x [512,1024]^T -> relu -> h1
    gemm_relu_kernel<true><<<dim3(N1 / 128, NPIX / 128), 256>>>(features, w1, b1, h1, C1, N1);
    // GEMM2: [32768,512] x [256,512]^T -> relu -> h2
    gemm_relu_kernel<false><<<dim3(N2 / 128, NPIX / 128), 256>>>(h1, w2, b2, h2, N1, N2);
    // layer3 + sigmoid + cam
    att_kernel<<<NPIX / 8, 256>>>(h2, w3, b3, cam, att_out);
    // peaks + coords
    peaks_kernel<<<B_, 256>>>(coords_out);
    // crops: 96 regions x 110592 float4
    crop_kernel<<<dim3(432, B_ * NREG), 256>>>(original, out);
}